// round 1
// baseline (speedup 1.0000x reference)
#include <cuda_runtime.h>

// Problem constants (fixed by reference)
constexpr int BB  = 4;     // batch
constexpr int SS  = 2048;  // seq
constexpr int HH  = 1024;  // hidden
constexpr int NH  = 16;    // heads
constexpr int HD  = 64;    // head dim
constexpr int SPL = 8;     // S split for gram partials

// Scratch (static device globals — allowed)
__device__ float g_Gpart[SPL][BB * NH][HD][HD];  // 8 MB
__device__ float g_V[BB][HH][HH];                // 16 MB

// ---------------------------------------------------------------------------
// Kernel 1: partial Gram matrices G[b,h] = X_{b,h}^T X_{b,h}, split over S.
// grid (64, 8), block 256 (16x16 threads, 4x4 outputs each)
// ---------------------------------------------------------------------------
__global__ void __launch_bounds__(256) gram_kernel(const float* __restrict__ x) {
    const int bh    = blockIdx.x;       // 0..63
    const int chunk = blockIdx.y;       // 0..7
    const int b = bh / NH, h = bh % NH;
    const float* Xb = x + (size_t)b * SS * HH + h * HD;

    __shared__ float Xs[32][HD];
    const int t  = threadIdx.x;
    const int ty = t >> 4, tx = t & 15;

    float acc[4][4] = {};
    const int s0 = chunk * (SS / SPL);  // 256 rows per chunk

    for (int tile = 0; tile < (SS / SPL) / 32; ++tile) {
        // load 32 rows x 64 cols of this head's slice
        for (int idx = t; idx < 32 * 64; idx += 256) {
            int r = idx >> 6, c = idx & 63;
            Xs[r][c] = Xb[(size_t)(s0 + tile * 32 + r) * HH + c];
        }
        __syncthreads();
#pragma unroll
        for (int ssi = 0; ssi < 32; ++ssi) {
            float4 xm = reinterpret_cast<float4*>(Xs[ssi])[ty];
            float4 xn = reinterpret_cast<float4*>(Xs[ssi])[tx];
            float m[4] = {xm.x, xm.y, xm.z, xm.w};
            float n[4] = {xn.x, xn.y, xn.z, xn.w};
#pragma unroll
            for (int i = 0; i < 4; ++i)
#pragma unroll
                for (int j = 0; j < 4; ++j) acc[i][j] += m[i] * n[j];
        }
        __syncthreads();
    }
#pragma unroll
    for (int i = 0; i < 4; ++i)
#pragma unroll
        for (int j = 0; j < 4; ++j)
            g_Gpart[chunk][bh][ty * 4 + i][tx * 4 + j] = acc[i][j];
}

// ---------------------------------------------------------------------------
// Kernel 2: combined weight  V_b[i, h*64+d] = sum_e W[h*64+e, i] * G[b,h][e,d]
// grid (64, 4), block 256. Each thread: one column i, all 64 d.
// ---------------------------------------------------------------------------
__global__ void __launch_bounds__(256) combine_kernel(const float* __restrict__ W) {
    const int bh = blockIdx.x;          // 0..63
    const int b = bh / NH, h = bh % NH;
    const int itile = blockIdx.y;       // 0..3 -> i base

    __shared__ float Gs[HD][HD];
    const int t = threadIdx.x;

    // sum the 8 partials into shared G
    for (int idx = t; idx < HD * HD; idx += 256) {
        int r = idx >> 6, c = idx & 63;
        float s = 0.f;
#pragma unroll
        for (int p = 0; p < SPL; ++p) s += g_Gpart[p][bh][r][c];
        Gs[r][c] = s;
    }
    __syncthreads();

    const int i = itile * 256 + t;      // 0..1023
    float acc[HD] = {};
#pragma unroll 4
    for (int e = 0; e < HD; ++e) {
        float w = W[(size_t)(h * HD + e) * HH + i];
#pragma unroll
        for (int d4 = 0; d4 < HD; d4 += 4) {
            float4 g = *reinterpret_cast<const float4*>(&Gs[e][d4]);
            acc[d4 + 0] += w * g.x;
            acc[d4 + 1] += w * g.y;
            acc[d4 + 2] += w * g.z;
            acc[d4 + 3] += w * g.w;
        }
    }
#pragma unroll
    for (int d = 0; d < HD; d += 4) {
        float4 v = {acc[d], acc[d + 1], acc[d + 2], acc[d + 3]};
        *reinterpret_cast<float4*>(&g_V[b][i][h * HD + d]) = v;
    }
}

// ---------------------------------------------------------------------------
// Kernel 3: O_b = x_b @ V_b   ([2048,1024] @ [1024,1024] per batch)
// classic 128x128x8 fp32 tiled GEMM, 256 threads, 8x8 microtile
// grid (8, 16, 4)
// ---------------------------------------------------------------------------
__global__ void __launch_bounds__(256) gemm_kernel(const float* __restrict__ Xall,
                                                   float* __restrict__ Out) {
    constexpr int BM = 128, BN = 128, BK = 8;
    const int b = blockIdx.z;
    const float* A  = Xall + (size_t)b * SS * HH;     // [2048,1024]
    const float* Bm = &g_V[b][0][0];                  // [1024,1024]
    float* C        = Out + (size_t)b * SS * HH;

    const int crow = blockIdx.y * BM;
    const int ccol = blockIdx.x * BN;

    __shared__ float As[BK][BM];
    __shared__ float Bs[BK][BN];

    const int t = threadIdx.x;
    const int arow  = t >> 1;            // 0..127
    const int acol4 = (t & 1) << 2;      // 0 or 4
    const int brow  = t >> 5;            // 0..7
    const int bcol4 = (t & 31) << 2;     // 0..124
    const int tr = t >> 4, tc = t & 15;

    float acc[8][8] = {};
    float regM[8], regN[8];

    for (int k0 = 0; k0 < HH; k0 += BK) {
        float4 av = *reinterpret_cast<const float4*>(
            &A[(size_t)(crow + arow) * HH + k0 + acol4]);
        As[acol4 + 0][arow] = av.x;
        As[acol4 + 1][arow] = av.y;
        As[acol4 + 2][arow] = av.z;
        As[acol4 + 3][arow] = av.w;
        float4 bv = *reinterpret_cast<const float4*>(
            &Bm[(size_t)(k0 + brow) * HH + ccol + bcol4]);
        *reinterpret_cast<float4*>(&Bs[brow][bcol4]) = bv;
        __syncthreads();
#pragma unroll
        for (int k = 0; k < BK; ++k) {
            float4 m0 = *reinterpret_cast<const float4*>(&As[k][tr * 8]);
            float4 m1 = *reinterpret_cast<const float4*>(&As[k][tr * 8 + 4]);
            float4 n0 = *reinterpret_cast<const float4*>(&Bs[k][tc * 8]);
            float4 n1 = *reinterpret_cast<const float4*>(&Bs[k][tc * 8 + 4]);
            regM[0] = m0.x; regM[1] = m0.y; regM[2] = m0.z; regM[3] = m0.w;
            regM[4] = m1.x; regM[5] = m1.y; regM[6] = m1.z; regM[7] = m1.w;
            regN[0] = n0.x; regN[1] = n0.y; regN[2] = n0.z; regN[3] = n0.w;
            regN[4] = n1.x; regN[5] = n1.y; regN[6] = n1.z; regN[7] = n1.w;
#pragma unroll
            for (int i = 0; i < 8; ++i)
#pragma unroll
                for (int j = 0; j < 8; ++j) acc[i][j] += regM[i] * regN[j];
        }
        __syncthreads();
    }

#pragma unroll
    for (int i = 0; i < 8; ++i) {
#pragma unroll
        for (int j = 0; j < 8; j += 4) {
            float4 v = {acc[i][j], acc[i][j + 1], acc[i][j + 2], acc[i][j + 3]};
            *reinterpret_cast<float4*>(
                &C[(size_t)(crow + tr * 8 + i) * HH + ccol + tc * 8 + j]) = v;
        }
    }
}

// ---------------------------------------------------------------------------
extern "C" void kernel_launch(void* const* d_in, const int* in_sizes, int n_in,
                              void* d_out, int out_size) {
    const float* x = (const float*)d_in[0];   // [4,2048,1024]
    const float* W = (const float*)d_in[1];   // [1024,1024]
    float* out = (float*)d_out;               // [4,2048,1024]

    gram_kernel<<<dim3(BB * NH, SPL), 256>>>(x);
    combine_kernel<<<dim3(BB * NH, 4), 256>>>(W);
    gemm_kernel<<<dim3(HH / 128, SS / 128, BB), 256>>>(x, out);
}

// round 3
// speedup vs baseline: 2.3079x; 2.3079x over previous
#include <cuda_runtime.h>
#include <cuda_fp16.h>
#include <cstdint>

// Problem constants
constexpr int BB  = 4;
constexpr int SS  = 2048;
constexpr int HH  = 1024;
constexpr int NH  = 16;
constexpr int HD  = 64;
constexpr int SPL = 8;

// Scratch (static device globals — allowed)
__device__ float g_Gpart[SPL][BB * NH][HD][HD];  // 8 MB
__device__ __half g_Vt[BB][HH][HH];              // 8.4 MB: Vt[n][k] = V[k][n], fp16

// ---------------------------------------------------------------------------
// Kernel 1: partial Gram matrices G[b,h] = X^T X (unchanged, known good)
// ---------------------------------------------------------------------------
__global__ void __launch_bounds__(256) gram_kernel(const float* __restrict__ x) {
    const int bh    = blockIdx.x;
    const int chunk = blockIdx.y;
    const int b = bh / NH, h = bh % NH;
    const float* Xb = x + (size_t)b * SS * HH + h * HD;

    __shared__ float Xs[32][HD];
    const int t  = threadIdx.x;
    const int ty = t >> 4, tx = t & 15;

    float acc[4][4] = {};
    const int s0 = chunk * (SS / SPL);

    for (int tile = 0; tile < (SS / SPL) / 32; ++tile) {
        for (int idx = t; idx < 32 * 64; idx += 256) {
            int r = idx >> 6, c = idx & 63;
            Xs[r][c] = Xb[(size_t)(s0 + tile * 32 + r) * HH + c];
        }
        __syncthreads();
#pragma unroll
        for (int ssi = 0; ssi < 32; ++ssi) {
            float4 xm = reinterpret_cast<float4*>(Xs[ssi])[ty];
            float4 xn = reinterpret_cast<float4*>(Xs[ssi])[tx];
            float m[4] = {xm.x, xm.y, xm.z, xm.w};
            float n[4] = {xn.x, xn.y, xn.z, xn.w};
#pragma unroll
            for (int i = 0; i < 4; ++i)
#pragma unroll
                for (int j = 0; j < 4; ++j) acc[i][j] += m[i] * n[j];
        }
        __syncthreads();
    }
#pragma unroll
    for (int i = 0; i < 4; ++i)
#pragma unroll
        for (int j = 0; j < 4; ++j)
            g_Gpart[chunk][bh][ty * 4 + i][tx * 4 + j] = acc[i][j];
}

// ---------------------------------------------------------------------------
// Kernel 2: combine -> Vt[n][k] in fp16 (fp32 accumulate, single rounding)
//   V[k=i][n=h*64+d] = sum_e W[h*64+e, i] * G[b,h][e,d]
// ---------------------------------------------------------------------------
__global__ void __launch_bounds__(256) combine_kernel(const float* __restrict__ W) {
    const int bh = blockIdx.x;
    const int b = bh / NH, h = bh % NH;
    const int itile = blockIdx.y;

    __shared__ float Gs[HD][HD];
    const int t = threadIdx.x;

    for (int idx = t; idx < HD * HD; idx += 256) {
        int r = idx >> 6, c = idx & 63;
        float s = 0.f;
#pragma unroll
        for (int p = 0; p < SPL; ++p) s += g_Gpart[p][bh][r][c];
        Gs[r][c] = s;
    }
    __syncthreads();

    const int i = itile * 256 + t;   // k index
    float acc[HD] = {};
#pragma unroll 4
    for (int e = 0; e < HD; ++e) {
        float w = W[(size_t)(h * HD + e) * HH + i];
#pragma unroll
        for (int d4 = 0; d4 < HD; d4 += 4) {
            float4 g = *reinterpret_cast<const float4*>(&Gs[e][d4]);
            acc[d4 + 0] += w * g.x;
            acc[d4 + 1] += w * g.y;
            acc[d4 + 2] += w * g.z;
            acc[d4 + 3] += w * g.w;
        }
    }
#pragma unroll
    for (int d = 0; d < HD; ++d)
        g_Vt[b][h * HD + d][i] = __float2half_rn(acc[d]);
}

// ---------------------------------------------------------------------------
// Kernel 3: HMMA GEMM  O_b = x_b @ V_b, fp16 2-pass (A hi/lo split, B fp16)
//   CTA tile 128x128, KT=32, double-buffered smem, 8 warps (4M x 2N)
// ---------------------------------------------------------------------------
constexpr int RS     = 40;            // halves per smem row (80 B, conflict-free)
constexpr int TILEH  = 128 * RS;      // 5120 halves per tile
constexpr int STAGEH = 3 * TILEH;     // Ahi, Alo, B
constexpr int GEMM_SMEM = 2 * STAGEH * 2;   // bytes = 61440

__device__ __forceinline__ void mma16816(float* c, const uint32_t* a, const uint32_t* b) {
    asm volatile(
        "mma.sync.aligned.m16n8k16.row.col.f32.f16.f16.f32 "
        "{%0,%1,%2,%3}, {%4,%5,%6,%7}, {%8,%9}, {%0,%1,%2,%3};"
        : "+f"(c[0]), "+f"(c[1]), "+f"(c[2]), "+f"(c[3])
        : "r"(a[0]), "r"(a[1]), "r"(a[2]), "r"(a[3]), "r"(b[0]), "r"(b[1]));
}

__global__ void __launch_bounds__(256) gemm_mma(const float* __restrict__ Xall,
                                                float* __restrict__ Out) {
    extern __shared__ __half sm[];
    const int t = threadIdx.x, lane = t & 31, wid = t >> 5;
    const int b = blockIdx.z;
    const int crow = blockIdx.y * 128, ccol = blockIdx.x * 128;
    const float* A  = Xall + (size_t)b * SS * HH;
    const __half* Bt = &g_Vt[b][0][0];

    const int m0 = (wid & 3) * 32;       // warp M offset (warp tile 32x64)
    const int n0 = (wid >> 2) * 64;      // warp N offset
    const int lr = lane >> 2, lc = (lane & 3) * 2;

    float acc[2][8][4];
#pragma unroll
    for (int mt = 0; mt < 2; ++mt)
#pragma unroll
        for (int nt = 0; nt < 8; ++nt)
#pragma unroll
            for (int j = 0; j < 4; ++j) acc[mt][nt][j] = 0.f;

    // global load mapping (constant per thread)
    const float*  aptr = A  + (size_t)(crow + (t >> 3)) * HH + (t & 7) * 4;
    const __half* bptr = Bt + (size_t)(ccol + (t >> 2)) * HH + (t & 3) * 8;
    const int sAoff = (t >> 3) * RS + (t & 7) * 4;
    const int sBoff = (t >> 2) * RS + (t & 3) * 8;

    float4 pa[4];
    float4 pb[2];

#define LDG_STAGE(k0)                                                           \
    do {                                                                        \
        _Pragma("unroll")                                                       \
        for (int q = 0; q < 4; ++q)                                             \
            pa[q] = *reinterpret_cast<const float4*>(aptr + (size_t)q * 32 * HH + (k0)); \
        _Pragma("unroll")                                                       \
        for (int q = 0; q < 2; ++q)                                             \
            pb[q] = *reinterpret_cast<const float4*>(                           \
                reinterpret_cast<const char*>(bptr + (size_t)q * 64 * HH + (k0))); \
    } while (0)

#define STS_STAGE(buf)                                                          \
    do {                                                                        \
        __half* Ah = sm + (buf) * STAGEH;                                       \
        __half* Al = Ah + TILEH;                                                \
        __half* Bs = Ah + 2 * TILEH;                                            \
        _Pragma("unroll")                                                       \
        for (int q = 0; q < 4; ++q) {                                           \
            float4 v = pa[q];                                                   \
            __half hx = __float2half_rn(v.x), hy = __float2half_rn(v.y);        \
            __half hz = __float2half_rn(v.z), hw = __float2half_rn(v.w);        \
            __half lx = __float2half_rn(v.x - __half2float(hx));                \
            __half ly = __float2half_rn(v.y - __half2float(hy));                \
            __half lz = __float2half_rn(v.z - __half2float(hz));                \
            __half lw = __float2half_rn(v.w - __half2float(hw));                \
            __half2* dh = reinterpret_cast<__half2*>(Ah + q * 32 * RS + sAoff); \
            dh[0] = __halves2half2(hx, hy);                                     \
            dh[1] = __halves2half2(hz, hw);                                     \
            __half2* dl = reinterpret_cast<__half2*>(Al + q * 32 * RS + sAoff); \
            dl[0] = __halves2half2(lx, ly);                                     \
            dl[1] = __halves2half2(lz, lw);                                     \
        }                                                                       \
        _Pragma("unroll")                                                       \
        for (int q = 0; q < 2; ++q)                                             \
            *reinterpret_cast<float4*>(Bs + q * 64 * RS + sBoff) = pb[q];       \
    } while (0)

#define COMPUTE_STAGE(buf)                                                      \
    do {                                                                        \
        const __half* Ah = sm + (buf) * STAGEH;                                 \
        const __half* Al = Ah + TILEH;                                          \
        const __half* Bs = Ah + 2 * TILEH;                                      \
        _Pragma("unroll")                                                       \
        for (int kk = 0; kk < 32; kk += 16) {                                   \
            uint32_t ah[2][4], al[2][4], bf[8][2];                              \
            _Pragma("unroll")                                                   \
            for (int mt = 0; mt < 2; ++mt) {                                    \
                int r = m0 + mt * 16 + lr;                                      \
                ah[mt][0] = *(const uint32_t*)(Ah + r * RS + kk + lc);          \
                ah[mt][1] = *(const uint32_t*)(Ah + (r + 8) * RS + kk + lc);    \
                ah[mt][2] = *(const uint32_t*)(Ah + r * RS + kk + 8 + lc);      \
                ah[mt][3] = *(const uint32_t*)(Ah + (r + 8) * RS + kk + 8 + lc);\
                al[mt][0] = *(const uint32_t*)(Al + r * RS + kk + lc);          \
                al[mt][1] = *(const uint32_t*)(Al + (r + 8) * RS + kk + lc);    \
                al[mt][2] = *(const uint32_t*)(Al + r * RS + kk + 8 + lc);      \
                al[mt][3] = *(const uint32_t*)(Al + (r + 8) * RS + kk + 8 + lc);\
            }                                                                   \
            _Pragma("unroll")                                                   \
            for (int nt = 0; nt < 8; ++nt) {                                    \
                int n = n0 + nt * 8 + lr;                                       \
                bf[nt][0] = *(const uint32_t*)(Bs + n * RS + kk + lc);          \
                bf[nt][1] = *(const uint32_t*)(Bs + n * RS + kk + 8 + lc);      \
            }                                                                   \
            _Pragma("unroll")                                                   \
            for (int mt = 0; mt < 2; ++mt)                                      \
                _Pragma("unroll")                                               \
                for (int nt = 0; nt < 8; ++nt) {                                \
                    mma16816(acc[mt][nt], ah[mt], bf[nt]);                      \
                    mma16816(acc[mt][nt], al[mt], bf[nt]);                      \
                }                                                               \
        }                                                                       \
    } while (0)

    LDG_STAGE(0);
    STS_STAGE(0);
    __syncthreads();

    for (int st = 0; st < HH / 32; ++st) {
        if (st < HH / 32 - 1) LDG_STAGE((st + 1) * 32);
        COMPUTE_STAGE(st & 1);
        if (st < HH / 32 - 1) STS_STAGE((st + 1) & 1);
        __syncthreads();
    }

    // Epilogue
    float* C = Out + (size_t)b * SS * HH;
#pragma unroll
    for (int mt = 0; mt < 2; ++mt)
#pragma unroll
        for (int nt = 0; nt < 8; ++nt) {
            int r = crow + m0 + mt * 16 + lr;
            int c = ccol + n0 + nt * 8 + lc;
            *reinterpret_cast<float2*>(&C[(size_t)r * HH + c]) =
                make_float2(acc[mt][nt][0], acc[mt][nt][1]);
            *reinterpret_cast<float2*>(&C[(size_t)(r + 8) * HH + c]) =
                make_float2(acc[mt][nt][2], acc[mt][nt][3]);
        }
}

// ---------------------------------------------------------------------------
extern "C" void kernel_launch(void* const* d_in, const int* in_sizes, int n_in,
                              void* d_out, int out_size) {
    const float* x = (const float*)d_in[0];   // [4,2048,1024]
    const float* W = (const float*)d_in[1];   // [1024,1024]
    float* out = (float*)d_out;               // [4,2048,1024]

    cudaFuncSetAttribute(gemm_mma, cudaFuncAttributeMaxDynamicSharedMemorySize,
                         GEMM_SMEM);

    gram_kernel<<<dim3(BB * NH, SPL), 256>>>(x);
    combine_kernel<<<dim3(BB * NH, 4), 256>>>(W);
    gemm_mma<<<dim3(HH / 128, SS / 128, BB), 256, GEMM_SMEM>>>(x, out);
}

// round 4
// speedup vs baseline: 3.9253x; 1.7008x over previous
#include <cuda_runtime.h>
#include <cuda_fp16.h>
#include <cstdint>

// Problem constants
constexpr int BB  = 4;
constexpr int SS  = 2048;
constexpr int HH  = 1024;
constexpr int NH  = 16;
constexpr int HD  = 64;
constexpr int SPL = 8;

// Scratch (static device globals — allowed)
__device__ float g_Gpart[SPL][BB * NH][HD][HD];  // 8 MB
__device__ __half g_Vt[BB][HH][HH];              // 8.4 MB: Vt[n][k] = V[k][n], fp16

// ---------------------------------------------------------------------------
// mma / ldmatrix helpers
// ---------------------------------------------------------------------------
__device__ __forceinline__ void mma16816(float* c, const uint32_t* a, const uint32_t* b) {
    asm volatile(
        "mma.sync.aligned.m16n8k16.row.col.f32.f16.f16.f32 "
        "{%0,%1,%2,%3}, {%4,%5,%6,%7}, {%8,%9}, {%0,%1,%2,%3};"
        : "+f"(c[0]), "+f"(c[1]), "+f"(c[2]), "+f"(c[3])
        : "r"(a[0]), "r"(a[1]), "r"(a[2]), "r"(a[3]), "r"(b[0]), "r"(b[1]));
}

__device__ __forceinline__ void ldsm4t(uint32_t* r, uint32_t saddr) {
    asm volatile("ldmatrix.sync.aligned.m8n8.x4.trans.shared.b16 {%0,%1,%2,%3}, [%4];"
                 : "=r"(r[0]), "=r"(r[1]), "=r"(r[2]), "=r"(r[3]) : "r"(saddr));
}

// ---------------------------------------------------------------------------
// Kernel 1: partial Gram via HMMA with fp16 hi/lo split (3 passes, lo*lo dropped)
//   G[b,h] = X^T X ;  X slice [2048 x 64], chunk of 256 s per CTA
//   X tile stored [s][d] in smem; A (=X^T) and B fragments via ldmatrix.trans
// ---------------------------------------------------------------------------
constexpr int GP = 72;   // smem row pitch (halves)

__global__ void __launch_bounds__(256) gram_mma(const float* __restrict__ x) {
    __shared__ __align__(16) __half Xh[64][GP];
    __shared__ __align__(16) __half Xl[64][GP];

    const int bh    = blockIdx.x;
    const int chunk = blockIdx.y;
    const int b = bh / NH, h = bh % NH;
    const float* Xb = x + (size_t)b * SS * HH + h * HD;
    const int s0 = chunk * (SS / SPL);       // 256 rows per CTA

    const int t = threadIdx.x, lane = t & 31, w = t >> 5;
    const int lr8 = lane & 7, g = lane >> 3;

    const int m0 = (w & 3) * 16;             // warp m-tile
    const int nb = (w >> 2) * 32;            // warp n-range (4 n-tiles of 8)

    float acc[4][4] = {};

    // per-lane ldmatrix addresses (row/col within tile; kk added later)
    uint32_t hbase = (uint32_t)__cvta_generic_to_shared(&Xh[0][0]);
    uint32_t lbase = (uint32_t)__cvta_generic_to_shared(&Xl[0][0]);
    // A: row = kk + (g&2?8:0)+lr8, col = m0 + (g&1?8:0)
    const uint32_t aoff = (uint32_t)((((g & 2) ? 8 : 0) + lr8) * GP + m0 + ((g & 1) ? 8 : 0)) * 2;
    // B: row = kk + (g&1?8:0)+lr8, col = n + (g&2?8:0)
    const uint32_t boff0 = (uint32_t)((((g & 1) ? 8 : 0) + lr8) * GP + nb + ((g & 2) ? 8 : 0)) * 2;
    const uint32_t boff1 = boff0 + 16 * 2;   // n + 16

    for (int sub = 0; sub < 4; ++sub) {
        // load 64 rows x 64 cols fp32, split to hi/lo fp16
#pragma unroll
        for (int q = 0; q < 4; ++q) {
            int idx = q * 256 + t;
            int r = idx >> 4, c = idx & 15;
            float4 v = *reinterpret_cast<const float4*>(
                &Xb[(size_t)(s0 + sub * 64 + r) * HH + c * 4]);
            __half hx = __float2half_rn(v.x), hy = __float2half_rn(v.y);
            __half hz = __float2half_rn(v.z), hw = __float2half_rn(v.w);
            __half lx = __float2half_rn(v.x - __half2float(hx));
            __half ly = __float2half_rn(v.y - __half2float(hy));
            __half lz = __float2half_rn(v.z - __half2float(hz));
            __half lw = __float2half_rn(v.w - __half2float(hw));
            __half2* dh = reinterpret_cast<__half2*>(&Xh[r][c * 4]);
            dh[0] = __halves2half2(hx, hy); dh[1] = __halves2half2(hz, hw);
            __half2* dl = reinterpret_cast<__half2*>(&Xl[r][c * 4]);
            dl[0] = __halves2half2(lx, ly); dl[1] = __halves2half2(lz, lw);
        }
        __syncthreads();

#pragma unroll
        for (int kk = 0; kk < 64; kk += 16) {
            const uint32_t kb = (uint32_t)(kk * GP * 2);
            uint32_t ah[4], al[4], bh0[4], bh1[4], bl0[4], bl1[4];
            ldsm4t(ah,  hbase + kb + aoff);
            ldsm4t(al,  lbase + kb + aoff);
            ldsm4t(bh0, hbase + kb + boff0);
            ldsm4t(bh1, hbase + kb + boff1);
            ldsm4t(bl0, lbase + kb + boff0);
            ldsm4t(bl1, lbase + kb + boff1);
#pragma unroll
            for (int nt = 0; nt < 4; ++nt) {
                const uint32_t* bh_ = (nt < 2) ? bh0 : bh1;
                const uint32_t* bl_ = (nt < 2) ? bl0 : bl1;
                uint32_t bhf[2] = {bh_[(nt & 1) * 2], bh_[(nt & 1) * 2 + 1]};
                uint32_t blf[2] = {bl_[(nt & 1) * 2], bl_[(nt & 1) * 2 + 1]};
                mma16816(acc[nt], ah, bhf);   // hi*hi
                mma16816(acc[nt], ah, blf);   // hi*lo
                mma16816(acc[nt], al, bhf);   // lo*hi
            }
        }
        __syncthreads();
    }

    // write partials
    const int lr = lane >> 2, lc = (lane & 3) * 2;
#pragma unroll
    for (int nt = 0; nt < 4; ++nt) {
        int n = nb + nt * 8 + lc;
        *reinterpret_cast<float2*>(&g_Gpart[chunk][bh][m0 + lr][n]) =
            make_float2(acc[nt][0], acc[nt][1]);
        *reinterpret_cast<float2*>(&g_Gpart[chunk][bh][m0 + lr + 8][n]) =
            make_float2(acc[nt][2], acc[nt][3]);
    }
}

// ---------------------------------------------------------------------------
// Kernel 2: combine -> Vt[n][k] in fp16
// ---------------------------------------------------------------------------
__global__ void __launch_bounds__(256) combine_kernel(const float* __restrict__ W) {
    const int bh = blockIdx.x;
    const int b = bh / NH, h = bh % NH;
    const int itile = blockIdx.y;

    __shared__ float Gs[HD][HD];
    const int t = threadIdx.x;

    for (int idx = t; idx < HD * HD; idx += 256) {
        int r = idx >> 6, c = idx & 63;
        float s = 0.f;
#pragma unroll
        for (int p = 0; p < SPL; ++p) s += g_Gpart[p][bh][r][c];
        Gs[r][c] = s;
    }
    __syncthreads();

    const int i = itile * 256 + t;
    float acc[HD] = {};
#pragma unroll 4
    for (int e = 0; e < HD; ++e) {
        float w = W[(size_t)(h * HD + e) * HH + i];
#pragma unroll
        for (int d4 = 0; d4 < HD; d4 += 4) {
            float4 g = *reinterpret_cast<const float4*>(&Gs[e][d4]);
            acc[d4 + 0] += w * g.x;
            acc[d4 + 1] += w * g.y;
            acc[d4 + 2] += w * g.z;
            acc[d4 + 3] += w * g.w;
        }
    }
#pragma unroll
    for (int d = 0; d < HD; ++d)
        g_Vt[b][h * HD + d][i] = __float2half_rn(acc[d]);
}

// ---------------------------------------------------------------------------
// Kernel 3: HMMA GEMM  O_b = x_b @ V_b, single-pass fp16
//   CTA tile 128x128, KT=32, double-buffered smem, 8 warps (4M x 2N)
// ---------------------------------------------------------------------------
constexpr int RS     = 40;            // halves per smem row (80 B)
constexpr int TILEH  = 128 * RS;
constexpr int STAGEH = 2 * TILEH;     // A, B
constexpr int GEMM_SMEM = 2 * STAGEH * 2;   // 40960 bytes

__global__ void __launch_bounds__(256) gemm_mma(const float* __restrict__ Xall,
                                                float* __restrict__ Out) {
    extern __shared__ __half sm[];
    const int t = threadIdx.x, lane = t & 31, wid = t >> 5;
    const int b = blockIdx.z;
    const int crow = blockIdx.y * 128, ccol = blockIdx.x * 128;
    const float* A  = Xall + (size_t)b * SS * HH;
    const __half* Bt = &g_Vt[b][0][0];

    const int m0 = (wid & 3) * 32;
    const int n0 = (wid >> 2) * 64;
    const int lr = lane >> 2, lc = (lane & 3) * 2;

    float acc[2][8][4];
#pragma unroll
    for (int mt = 0; mt < 2; ++mt)
#pragma unroll
        for (int nt = 0; nt < 8; ++nt)
#pragma unroll
            for (int j = 0; j < 4; ++j) acc[mt][nt][j] = 0.f;

    const float*  aptr = A  + (size_t)(crow + (t >> 3)) * HH + (t & 7) * 4;
    const __half* bptr = Bt + (size_t)(ccol + (t >> 2)) * HH + (t & 3) * 8;
    const int sAoff = (t >> 3) * RS + (t & 7) * 4;
    const int sBoff = (t >> 2) * RS + (t & 3) * 8;

    float4 pa[4];
    float4 pb[2];

#define LDG_STAGE(k0)                                                           \
    do {                                                                        \
        _Pragma("unroll")                                                       \
        for (int q = 0; q < 4; ++q)                                             \
            pa[q] = *reinterpret_cast<const float4*>(aptr + (size_t)q * 32 * HH + (k0)); \
        _Pragma("unroll")                                                       \
        for (int q = 0; q < 2; ++q)                                             \
            pb[q] = *reinterpret_cast<const float4*>(                           \
                reinterpret_cast<const char*>(bptr + (size_t)q * 64 * HH + (k0))); \
    } while (0)

#define STS_STAGE(buf)                                                          \
    do {                                                                        \
        __half* Ah = sm + (buf) * STAGEH;                                       \
        __half* Bs = Ah + TILEH;                                                \
        _Pragma("unroll")                                                       \
        for (int q = 0; q < 4; ++q) {                                           \
            float4 v = pa[q];                                                   \
            __half2* dh = reinterpret_cast<__half2*>(Ah + q * 32 * RS + sAoff); \
            dh[0] = __halves2half2(__float2half_rn(v.x), __float2half_rn(v.y)); \
            dh[1] = __halves2half2(__float2half_rn(v.z), __float2half_rn(v.w)); \
        }                                                                       \
        _Pragma("unroll")                                                       \
        for (int q = 0; q < 2; ++q)                                             \
            *reinterpret_cast<float4*>(Bs + q * 64 * RS + sBoff) = pb[q];       \
    } while (0)

#define COMPUTE_STAGE(buf)                                                      \
    do {                                                                        \
        const __half* Ah = sm + (buf) * STAGEH;                                 \
        const __half* Bs = Ah + TILEH;                                          \
        _Pragma("unroll")                                                       \
        for (int kk = 0; kk < 32; kk += 16) {                                   \
            uint32_t ah[2][4], bf[8][2];                                        \
            _Pragma("unroll")                                                   \
            for (int mt = 0; mt < 2; ++mt) {                                    \
                int r = m0 + mt * 16 + lr;                                      \
                ah[mt][0] = *(const uint32_t*)(Ah + r * RS + kk + lc);          \
                ah[mt][1] = *(const uint32_t*)(Ah + (r + 8) * RS + kk + lc);    \
                ah[mt][2] = *(const uint32_t*)(Ah + r * RS + kk + 8 + lc);      \
                ah[mt][3] = *(const uint32_t*)(Ah + (r + 8) * RS + kk + 8 + lc);\
            }                                                                   \
            _Pragma("unroll")                                                   \
            for (int nt = 0; nt < 8; ++nt) {                                    \
                int n = n0 + nt * 8 + lr;                                       \
                bf[nt][0] = *(const uint32_t*)(Bs + n * RS + kk + lc);          \
                bf[nt][1] = *(const uint32_t*)(Bs + n * RS + kk + 8 + lc);      \
            }                                                                   \
            _Pragma("unroll")                                                   \
            for (int mt = 0; mt < 2; ++mt)                                      \
                _Pragma("unroll")                                               \
                for (int nt = 0; nt < 8; ++nt)                                  \
                    mma16816(acc[mt][nt], ah[mt], bf[nt]);                      \
        }                                                                       \
    } while (0)

    LDG_STAGE(0);
    STS_STAGE(0);
    __syncthreads();

    for (int st = 0; st < HH / 32; ++st) {
        if (st < HH / 32 - 1) LDG_STAGE((st + 1) * 32);
        COMPUTE_STAGE(st & 1);
        if (st < HH / 32 - 1) STS_STAGE((st + 1) & 1);
        __syncthreads();
    }

    float* C = Out + (size_t)b * SS * HH;
#pragma unroll
    for (int mt = 0; mt < 2; ++mt)
#pragma unroll
        for (int nt = 0; nt < 8; ++nt) {
            int r = crow + m0 + mt * 16 + lr;
            int c = ccol + n0 + nt * 8 + lc;
            *reinterpret_cast<float2*>(&C[(size_t)r * HH + c]) =
                make_float2(acc[mt][nt][0], acc[mt][nt][1]);
            *reinterpret_cast<float2*>(&C[(size_t)(r + 8) * HH + c]) =
                make_float2(acc[mt][nt][2], acc[mt][nt][3]);
        }
}

// ---------------------------------------------------------------------------
extern "C" void kernel_launch(void* const* d_in, const int* in_sizes, int n_in,
                              void* d_out, int out_size) {
    const float* x = (const float*)d_in[0];   // [4,2048,1024]
    const float* W = (const float*)d_in[1];   // [1024,1024]
    float* out = (float*)d_out;               // [4,2048,1024]

    cudaFuncSetAttribute(gemm_mma, cudaFuncAttributeMaxDynamicSharedMemorySize,
                         GEMM_SMEM);

    gram_mma<<<dim3(BB * NH, SPL), 256>>>(x);
    combine_kernel<<<dim3(BB * NH, 4), 256>>>(W);
    gemm_mma<<<dim3(HH / 128, SS / 128, BB), 256, GEMM_SMEM>>>(x, out);
}

// round 5
// speedup vs baseline: 4.0423x; 1.0298x over previous
#include <cuda_runtime.h>
#include <cuda_fp16.h>
#include <cstdint>

// Problem constants
constexpr int BB  = 4;
constexpr int SS  = 2048;
constexpr int HH  = 1024;
constexpr int NH  = 16;
constexpr int HD  = 64;
constexpr int SPL = 8;

// Scratch (static device globals — allowed)
__device__ float g_Gpart[SPL][BB * NH][HD][HD];  // 8 MB
__device__ __half g_Vt[BB][HH][HH];              // 8.4 MB: Vt[n][k]
__device__ __half g_Xh[BB][SS][HH];              // 16.8 MB: x rounded to fp16

// ---------------------------------------------------------------------------
// helpers
// ---------------------------------------------------------------------------
__device__ __forceinline__ void mma16816(float* c, const uint32_t* a, const uint32_t* b) {
    asm volatile(
        "mma.sync.aligned.m16n8k16.row.col.f32.f16.f16.f32 "
        "{%0,%1,%2,%3}, {%4,%5,%6,%7}, {%8,%9}, {%0,%1,%2,%3};"
        : "+f"(c[0]), "+f"(c[1]), "+f"(c[2]), "+f"(c[3])
        : "r"(a[0]), "r"(a[1]), "r"(a[2]), "r"(a[3]), "r"(b[0]), "r"(b[1]));
}
__device__ __forceinline__ void ldsm4(uint32_t* r, uint32_t saddr) {
    asm volatile("ldmatrix.sync.aligned.m8n8.x4.shared.b16 {%0,%1,%2,%3}, [%4];"
                 : "=r"(r[0]), "=r"(r[1]), "=r"(r[2]), "=r"(r[3]) : "r"(saddr));
}
__device__ __forceinline__ void ldsm4t(uint32_t* r, uint32_t saddr) {
    asm volatile("ldmatrix.sync.aligned.m8n8.x4.trans.shared.b16 {%0,%1,%2,%3}, [%4];"
                 : "=r"(r[0]), "=r"(r[1]), "=r"(r[2]), "=r"(r[3]) : "r"(saddr));
}
__device__ __forceinline__ void cpasync16(uint32_t dst, const void* src) {
    asm volatile("cp.async.cg.shared.global [%0], [%1], 16;" :: "r"(dst), "l"(src));
}
#define CP_COMMIT() asm volatile("cp.async.commit_group;" ::: "memory")
#define CP_WAIT2()  asm volatile("cp.async.wait_group 2;" ::: "memory")

// ---------------------------------------------------------------------------
// Kernel 1: partial Gram via HMMA (hi/lo split, 3 passes) + emit g_Xh (fp16 hi)
// ---------------------------------------------------------------------------
constexpr int GP = 72;   // smem row pitch (halves)

__global__ void __launch_bounds__(256) gram_mma(const float* __restrict__ x) {
    __shared__ __align__(16) __half Xhs[64][GP];
    __shared__ __align__(16) __half Xls[64][GP];

    const int bh    = blockIdx.x;
    const int chunk = blockIdx.y;
    const int b = bh / NH, h = bh % NH;
    const float* Xb = x + (size_t)b * SS * HH + h * HD;
    const int s0 = chunk * (SS / SPL);

    const int t = threadIdx.x, lane = t & 31, w = t >> 5;
    const int lr8 = lane & 7, g = lane >> 3;

    const int m0 = (w & 3) * 16;
    const int nb = (w >> 2) * 32;

    float acc[4][4] = {};

    uint32_t hbase = (uint32_t)__cvta_generic_to_shared(&Xhs[0][0]);
    uint32_t lbase = (uint32_t)__cvta_generic_to_shared(&Xls[0][0]);
    const uint32_t aoff = (uint32_t)((((g & 2) ? 8 : 0) + lr8) * GP + m0 + ((g & 1) ? 8 : 0)) * 2;
    const uint32_t boff0 = (uint32_t)((((g & 1) ? 8 : 0) + lr8) * GP + nb + ((g & 2) ? 8 : 0)) * 2;
    const uint32_t boff1 = boff0 + 16 * 2;

    for (int sub = 0; sub < 4; ++sub) {
#pragma unroll
        for (int q = 0; q < 4; ++q) {
            int idx = q * 256 + t;
            int r = idx >> 4, c = idx & 15;
            int srow = s0 + sub * 64 + r;
            float4 v = *reinterpret_cast<const float4*>(&Xb[(size_t)srow * HH + c * 4]);
            __half hx = __float2half_rn(v.x), hy = __float2half_rn(v.y);
            __half hz = __float2half_rn(v.z), hw = __float2half_rn(v.w);
            __half lx = __float2half_rn(v.x - __half2float(hx));
            __half ly = __float2half_rn(v.y - __half2float(hy));
            __half lz = __float2half_rn(v.z - __half2float(hz));
            __half lw = __float2half_rn(v.w - __half2float(hw));
            __half2 p0 = __halves2half2(hx, hy), p1 = __halves2half2(hz, hw);
            __half2* dh = reinterpret_cast<__half2*>(&Xhs[r][c * 4]);
            dh[0] = p0; dh[1] = p1;
            __half2* dl = reinterpret_cast<__half2*>(&Xls[r][c * 4]);
            dl[0] = __halves2half2(lx, ly); dl[1] = __halves2half2(lz, lw);
            // emit fp16 x for the big GEMM
            __half2* gx = reinterpret_cast<__half2*>(&g_Xh[b][srow][h * HD + c * 4]);
            gx[0] = p0; gx[1] = p1;
        }
        __syncthreads();

#pragma unroll
        for (int kk = 0; kk < 64; kk += 16) {
            const uint32_t kb = (uint32_t)(kk * GP * 2);
            uint32_t ah[4], al[4], bh0[4], bh1[4], bl0[4], bl1[4];
            ldsm4t(ah,  hbase + kb + aoff);
            ldsm4t(al,  lbase + kb + aoff);
            ldsm4t(bh0, hbase + kb + boff0);
            ldsm4t(bh1, hbase + kb + boff1);
            ldsm4t(bl0, lbase + kb + boff0);
            ldsm4t(bl1, lbase + kb + boff1);
#pragma unroll
            for (int nt = 0; nt < 4; ++nt) {
                const uint32_t* bh_ = (nt < 2) ? bh0 : bh1;
                const uint32_t* bl_ = (nt < 2) ? bl0 : bl1;
                uint32_t bhf[2] = {bh_[(nt & 1) * 2], bh_[(nt & 1) * 2 + 1]};
                uint32_t blf[2] = {bl_[(nt & 1) * 2], bl_[(nt & 1) * 2 + 1]};
                mma16816(acc[nt], ah, bhf);
                mma16816(acc[nt], ah, blf);
                mma16816(acc[nt], al, bhf);
            }
        }
        __syncthreads();
    }

    const int lr = lane >> 2, lc = (lane & 3) * 2;
#pragma unroll
    for (int nt = 0; nt < 4; ++nt) {
        int n = nb + nt * 8 + lc;
        *reinterpret_cast<float2*>(&g_Gpart[chunk][bh][m0 + lr][n]) =
            make_float2(acc[nt][0], acc[nt][1]);
        *reinterpret_cast<float2*>(&g_Gpart[chunk][bh][m0 + lr + 8][n]) =
            make_float2(acc[nt][2], acc[nt][3]);
    }
}

// ---------------------------------------------------------------------------
// Kernel 2: combine -> Vt[n][k] in fp16
// ---------------------------------------------------------------------------
__global__ void __launch_bounds__(256) combine_kernel(const float* __restrict__ W) {
    const int bh = blockIdx.x;
    const int b = bh / NH, h = bh % NH;
    const int itile = blockIdx.y;

    __shared__ float Gs[HD][HD];
    const int t = threadIdx.x;

    for (int idx = t; idx < HD * HD; idx += 256) {
        int r = idx >> 6, c = idx & 63;
        float s = 0.f;
#pragma unroll
        for (int p = 0; p < SPL; ++p) s += g_Gpart[p][bh][r][c];
        Gs[r][c] = s;
    }
    __syncthreads();

    const int i = itile * 256 + t;
    float acc[HD] = {};
#pragma unroll 4
    for (int e = 0; e < HD; ++e) {
        float w = W[(size_t)(h * HD + e) * HH + i];
#pragma unroll
        for (int d4 = 0; d4 < HD; d4 += 4) {
            float4 g = *reinterpret_cast<const float4*>(&Gs[e][d4]);
            acc[d4 + 0] += w * g.x;
            acc[d4 + 1] += w * g.y;
            acc[d4 + 2] += w * g.z;
            acc[d4 + 3] += w * g.w;
        }
    }
#pragma unroll
    for (int d = 0; d < HD; ++d)
        g_Vt[b][h * HD + d][i] = __float2half_rn(acc[d]);
}

// ---------------------------------------------------------------------------
// Kernel 3: pure-fp16 HMMA GEMM with cp.async 4-stage pipeline + ldmatrix
//   O_b = Xh_b @ Vt_b^T ; CTA tile 128x128, KT=32
// ---------------------------------------------------------------------------
constexpr int KT    = 32;
constexpr int PITCH = 40;                 // halves per smem row
constexpr int OPH   = 128 * PITCH;        // halves per operand tile
constexpr int STH   = 2 * OPH;            // halves per stage
constexpr int NST   = 4;
constexpr int GEMM_SMEM = NST * STH * 2;  // 81920 bytes

__global__ void __launch_bounds__(256) gemm_mma(float* __restrict__ Out) {
    extern __shared__ __half sm[];
    const int t = threadIdx.x, lane = t & 31, wid = t >> 5;
    const int b = blockIdx.z;
    const int crow = blockIdx.y * 128, ccol = blockIdx.x * 128;
    const __half* Ag = &g_Xh[b][0][0];
    const __half* Bg = &g_Vt[b][0][0];

    const uint32_t smu = (uint32_t)__cvta_generic_to_shared(sm);

    const int m0 = (wid & 3) * 32;
    const int n0 = (wid >> 2) * 64;
    const int lr8 = lane & 7, g = lane >> 3;

    // ldmatrix per-lane byte offsets (within operand tile)
    uint32_t aoffb[2], boffb[4];
#pragma unroll
    for (int mt = 0; mt < 2; ++mt)
        aoffb[mt] = (uint32_t)(((m0 + mt * 16 + ((g & 1) ? 8 : 0) + lr8) * PITCH
                                + ((g & 2) ? 8 : 0)) * 2);
#pragma unroll
    for (int j = 0; j < 4; ++j)
        boffb[j] = (uint32_t)(((n0 + j * 16 + ((g & 1) ? 8 : 0) + lr8) * PITCH
                               + ((g & 2) ? 8 : 0)) * 2);

    // cp.async mapping: idx = q*256+t, r = idx>>2, c = idx&3 (16B chunks)
    const int cpr = t >> 2, cpc = t & 3;
    const __half* aSrc = Ag + (size_t)(crow + cpr) * HH + cpc * 8;
    const __half* bSrc = Bg + (size_t)(ccol + cpr) * HH + cpc * 8;
    const uint32_t aDst = smu + (uint32_t)((cpr * PITCH + cpc * 8) * 2);
    const uint32_t bDst = aDst + OPH * 2;

    float acc[2][8][4];
#pragma unroll
    for (int mt = 0; mt < 2; ++mt)
#pragma unroll
        for (int nt = 0; nt < 8; ++nt)
#pragma unroll
            for (int j = 0; j < 4; ++j) acc[mt][nt][j] = 0.f;

#define ISSUE_STAGE(st, buf)                                                    \
    do {                                                                        \
        const int k0 = (st) * KT;                                               \
        const uint32_t sb = (uint32_t)((buf) * STH * 2);                        \
        _Pragma("unroll")                                                       \
        for (int q = 0; q < 2; ++q) {                                           \
            cpasync16(aDst + sb + q * 64 * PITCH * 2,                           \
                      aSrc + (size_t)q * 64 * HH + k0);                         \
            cpasync16(bDst + sb + q * 64 * PITCH * 2,                           \
                      bSrc + (size_t)q * 64 * HH + k0);                         \
        }                                                                       \
    } while (0)

    ISSUE_STAGE(0, 0); CP_COMMIT();
    ISSUE_STAGE(1, 1); CP_COMMIT();
    ISSUE_STAGE(2, 2); CP_COMMIT();

    const int NSTAGES = HH / KT;   // 32
    for (int st = 0; st < NSTAGES; ++st) {
        CP_WAIT2();
        __syncthreads();

        const uint32_t baseA = smu + (uint32_t)((st & 3) * STH * 2);
        const uint32_t baseB = baseA + OPH * 2;
#pragma unroll
        for (int kk = 0; kk < KT; kk += 16) {
            const uint32_t kb = (uint32_t)(kk * 2);
            uint32_t af[2][4], bf[4][4];
#pragma unroll
            for (int mt = 0; mt < 2; ++mt) ldsm4(af[mt], baseA + aoffb[mt] + kb);
#pragma unroll
            for (int j = 0; j < 4; ++j)    ldsm4(bf[j],  baseB + boffb[j] + kb);
#pragma unroll
            for (int mt = 0; mt < 2; ++mt)
#pragma unroll
                for (int nt = 0; nt < 8; ++nt) {
                    uint32_t bb[2] = {bf[nt >> 1][(nt & 1) ? 1 : 0],
                                      bf[nt >> 1][(nt & 1) ? 3 : 2]};
                    mma16816(acc[mt][nt], af[mt], bb);
                }
        }
        __syncthreads();
        if (st + 3 < NSTAGES) ISSUE_STAGE(st + 3, (st + 3) & 3);
        CP_COMMIT();
    }

    // Epilogue
    const int lr = lane >> 2, lc = (lane & 3) * 2;
    float* C = Out + (size_t)b * SS * HH;
#pragma unroll
    for (int mt = 0; mt < 2; ++mt)
#pragma unroll
        for (int nt = 0; nt < 8; ++nt) {
            int r = crow + m0 + mt * 16 + lr;
            int c = ccol + n0 + nt * 8 + lc;
            *reinterpret_cast<float2*>(&C[(size_t)r * HH + c]) =
                make_float2(acc[mt][nt][0], acc[mt][nt][1]);
            *reinterpret_cast<float2*>(&C[(size_t)(r + 8) * HH + c]) =
                make_float2(acc[mt][nt][2], acc[mt][nt][3]);
        }
}

// ---------------------------------------------------------------------------
extern "C" void kernel_launch(void* const* d_in, const int* in_sizes, int n_in,
                              void* d_out, int out_size) {
    const float* x = (const float*)d_in[0];   // [4,2048,1024]
    const float* W = (const float*)d_in[1];   // [1024,1024]
    float* out = (float*)d_out;               // [4,2048,1024]

    cudaFuncSetAttribute(gemm_mma, cudaFuncAttributeMaxDynamicSharedMemorySize,
                         GEMM_SMEM);

    gram_mma<<<dim3(BB * NH, SPL), 256>>>(x);
    combine_kernel<<<dim3(BB * NH, 4), 256>>>(W);
    gemm_mma<<<dim3(HH / 128, SS / 128, BB), 256, GEMM_SMEM>>>(out);
}

// round 6
// speedup vs baseline: 4.2555x; 1.0527x over previous
#include <cuda_runtime.h>
#include <cuda_fp16.h>
#include <cstdint>

// Problem constants
constexpr int BB  = 4;
constexpr int SS  = 2048;
constexpr int HH  = 1024;
constexpr int NH  = 16;
constexpr int HD  = 64;
constexpr int SPL = 8;

// Scratch (static device globals — allowed)
__device__ float g_Gpart[SPL][BB * NH][HD][HD];  // 8 MB
__device__ __half g_Vt[BB][HH][HH];              // 8.4 MB: Vt[n][k]
__device__ __half g_Xh[BB][SS][HH];              // 16.8 MB: x rounded to fp16

// ---------------------------------------------------------------------------
// helpers
// ---------------------------------------------------------------------------
__device__ __forceinline__ void mma16816(float* c, const uint32_t* a, const uint32_t* b) {
    asm volatile(
        "mma.sync.aligned.m16n8k16.row.col.f32.f16.f16.f32 "
        "{%0,%1,%2,%3}, {%4,%5,%6,%7}, {%8,%9}, {%0,%1,%2,%3};"
        : "+f"(c[0]), "+f"(c[1]), "+f"(c[2]), "+f"(c[3])
        : "r"(a[0]), "r"(a[1]), "r"(a[2]), "r"(a[3]), "r"(b[0]), "r"(b[1]));
}
__device__ __forceinline__ void ldsm4(uint32_t* r, uint32_t saddr) {
    asm volatile("ldmatrix.sync.aligned.m8n8.x4.shared.b16 {%0,%1,%2,%3}, [%4];"
                 : "=r"(r[0]), "=r"(r[1]), "=r"(r[2]), "=r"(r[3]) : "r"(saddr));
}
__device__ __forceinline__ void ldsm4t(uint32_t* r, uint32_t saddr) {
    asm volatile("ldmatrix.sync.aligned.m8n8.x4.trans.shared.b16 {%0,%1,%2,%3}, [%4];"
                 : "=r"(r[0]), "=r"(r[1]), "=r"(r[2]), "=r"(r[3]) : "r"(saddr));
}
__device__ __forceinline__ void cpasync16(uint32_t dst, const void* src) {
    asm volatile("cp.async.cg.shared.global [%0], [%1], 16;" :: "r"(dst), "l"(src));
}
#define CP_COMMIT() asm volatile("cp.async.commit_group;" ::: "memory")
#define CP_WAIT2()  asm volatile("cp.async.wait_group 2;" ::: "memory")

// ---------------------------------------------------------------------------
// Kernel 1: partial Gram via HMMA (hi/lo split, 3 passes) + emit g_Xh (fp16 hi)
// ---------------------------------------------------------------------------
constexpr int GP = 72;   // smem row pitch (halves)

__global__ void __launch_bounds__(256) gram_mma(const float* __restrict__ x) {
    __shared__ __align__(16) __half Xhs[64][GP];
    __shared__ __align__(16) __half Xls[64][GP];

    const int bh    = blockIdx.x;
    const int chunk = blockIdx.y;
    const int b = bh / NH, h = bh % NH;
    const float* Xb = x + (size_t)b * SS * HH + h * HD;
    const int s0 = chunk * (SS / SPL);

    const int t = threadIdx.x, lane = t & 31, w = t >> 5;
    const int lr8 = lane & 7, g = lane >> 3;

    const int m0 = (w & 3) * 16;
    const int nb = (w >> 2) * 32;

    float acc[4][4] = {};

    uint32_t hbase = (uint32_t)__cvta_generic_to_shared(&Xhs[0][0]);
    uint32_t lbase = (uint32_t)__cvta_generic_to_shared(&Xls[0][0]);
    const uint32_t aoff = (uint32_t)((((g & 2) ? 8 : 0) + lr8) * GP + m0 + ((g & 1) ? 8 : 0)) * 2;
    const uint32_t boff0 = (uint32_t)((((g & 1) ? 8 : 0) + lr8) * GP + nb + ((g & 2) ? 8 : 0)) * 2;
    const uint32_t boff1 = boff0 + 16 * 2;

    for (int sub = 0; sub < 4; ++sub) {
#pragma unroll
        for (int q = 0; q < 4; ++q) {
            int idx = q * 256 + t;
            int r = idx >> 4, c = idx & 15;
            int srow = s0 + sub * 64 + r;
            float4 v = *reinterpret_cast<const float4*>(&Xb[(size_t)srow * HH + c * 4]);
            __half hx = __float2half_rn(v.x), hy = __float2half_rn(v.y);
            __half hz = __float2half_rn(v.z), hw = __float2half_rn(v.w);
            __half lx = __float2half_rn(v.x - __half2float(hx));
            __half ly = __float2half_rn(v.y - __half2float(hy));
            __half lz = __float2half_rn(v.z - __half2float(hz));
            __half lw = __float2half_rn(v.w - __half2float(hw));
            __half2 p0 = __halves2half2(hx, hy), p1 = __halves2half2(hz, hw);
            __half2* dh = reinterpret_cast<__half2*>(&Xhs[r][c * 4]);
            dh[0] = p0; dh[1] = p1;
            __half2* dl = reinterpret_cast<__half2*>(&Xls[r][c * 4]);
            dl[0] = __halves2half2(lx, ly); dl[1] = __halves2half2(lz, lw);
            __half2* gx = reinterpret_cast<__half2*>(&g_Xh[b][srow][h * HD + c * 4]);
            gx[0] = p0; gx[1] = p1;
        }
        __syncthreads();

#pragma unroll
        for (int kk = 0; kk < 64; kk += 16) {
            const uint32_t kb = (uint32_t)(kk * GP * 2);
            uint32_t ah[4], al[4], bh0[4], bh1[4], bl0[4], bl1[4];
            ldsm4t(ah,  hbase + kb + aoff);
            ldsm4t(al,  lbase + kb + aoff);
            ldsm4t(bh0, hbase + kb + boff0);
            ldsm4t(bh1, hbase + kb + boff1);
            ldsm4t(bl0, lbase + kb + boff0);
            ldsm4t(bl1, lbase + kb + boff1);
#pragma unroll
            for (int nt = 0; nt < 4; ++nt) {
                const uint32_t* bh_ = (nt < 2) ? bh0 : bh1;
                const uint32_t* bl_ = (nt < 2) ? bl0 : bl1;
                uint32_t bhf[2] = {bh_[(nt & 1) * 2], bh_[(nt & 1) * 2 + 1]};
                uint32_t blf[2] = {bl_[(nt & 1) * 2], bl_[(nt & 1) * 2 + 1]};
                mma16816(acc[nt], ah, bhf);
                mma16816(acc[nt], ah, blf);
                mma16816(acc[nt], al, bhf);
            }
        }
        __syncthreads();
    }

    const int lr = lane >> 2, lc = (lane & 3) * 2;
#pragma unroll
    for (int nt = 0; nt < 4; ++nt) {
        int n = nb + nt * 8 + lc;
        *reinterpret_cast<float2*>(&g_Gpart[chunk][bh][m0 + lr][n]) =
            make_float2(acc[nt][0], acc[nt][1]);
        *reinterpret_cast<float2*>(&g_Gpart[chunk][bh][m0 + lr + 8][n]) =
            make_float2(acc[nt][2], acc[nt][3]);
    }
}

// ---------------------------------------------------------------------------
// Kernel 2: combine -> Vt[n][k] in fp16
// ---------------------------------------------------------------------------
__global__ void __launch_bounds__(256) combine_kernel(const float* __restrict__ W) {
    const int bh = blockIdx.x;
    const int b = bh / NH, h = bh % NH;
    const int itile = blockIdx.y;

    __shared__ float Gs[HD][HD];
    const int t = threadIdx.x;

    for (int idx = t; idx < HD * HD; idx += 256) {
        int r = idx >> 6, c = idx & 63;
        float s = 0.f;
#pragma unroll
        for (int p = 0; p < SPL; ++p) s += g_Gpart[p][bh][r][c];
        Gs[r][c] = s;
    }
    __syncthreads();

    const int i = itile * 256 + t;
    float acc[HD] = {};
#pragma unroll 4
    for (int e = 0; e < HD; ++e) {
        float w = W[(size_t)(h * HD + e) * HH + i];
#pragma unroll
        for (int d4 = 0; d4 < HD; d4 += 4) {
            float4 g = *reinterpret_cast<const float4*>(&Gs[e][d4]);
            acc[d4 + 0] += w * g.x;
            acc[d4 + 1] += w * g.y;
            acc[d4 + 2] += w * g.z;
            acc[d4 + 3] += w * g.w;
        }
    }
#pragma unroll
    for (int d = 0; d < HD; ++d)
        g_Vt[b][h * HD + d][i] = __float2half_rn(acc[d]);
}

// ---------------------------------------------------------------------------
// Kernel 3: pure-fp16 HMMA GEMM, 4 warps x (64x64), single sync/iter
//   CTA tile 128x128, KT=32, 4-stage cp.async ring
// ---------------------------------------------------------------------------
constexpr int KT    = 32;
constexpr int PITCH = 40;                 // halves per smem row
constexpr int OPH   = 128 * PITCH;        // halves per operand tile
constexpr int STH   = 2 * OPH;            // halves per stage
constexpr int NST   = 4;
constexpr int GEMM_SMEM = NST * STH * 2;  // 81920 bytes

__global__ void __launch_bounds__(128, 2) gemm_mma(float* __restrict__ Out) {
    extern __shared__ __half sm[];
    const int t = threadIdx.x, lane = t & 31, wid = t >> 5;
    const int b = blockIdx.z;
    const int crow = blockIdx.y * 128, ccol = blockIdx.x * 128;
    const __half* Ag = &g_Xh[b][0][0];
    const __half* Bg = &g_Vt[b][0][0];

    const uint32_t smu = (uint32_t)__cvta_generic_to_shared(sm);

    const int m0 = (wid & 1) * 64;       // 2x2 warp grid, warp tile 64x64
    const int n0 = (wid >> 1) * 64;
    const int lr8 = lane & 7, g = lane >> 3;

    uint32_t aoffb[4], boffb[4];
#pragma unroll
    for (int mt = 0; mt < 4; ++mt)
        aoffb[mt] = (uint32_t)(((m0 + mt * 16 + ((g & 1) ? 8 : 0) + lr8) * PITCH
                                + ((g & 2) ? 8 : 0)) * 2);
#pragma unroll
    for (int j = 0; j < 4; ++j)
        boffb[j] = (uint32_t)(((n0 + j * 16 + ((g & 1) ? 8 : 0) + lr8) * PITCH
                               + ((g & 2) ? 8 : 0)) * 2);

    // cp.async mapping: 128 threads, r = t>>2 (0..31), c = t&3 (16B chunks)
    const int cpr = t >> 2, cpc = t & 3;
    const __half* aSrc = Ag + (size_t)(crow + cpr) * HH + cpc * 8;
    const __half* bSrc = Bg + (size_t)(ccol + cpr) * HH + cpc * 8;
    const uint32_t aDst = smu + (uint32_t)((cpr * PITCH + cpc * 8) * 2);
    const uint32_t bDst = aDst + OPH * 2;

    float acc[4][8][4];
#pragma unroll
    for (int mt = 0; mt < 4; ++mt)
#pragma unroll
        for (int nt = 0; nt < 8; ++nt)
#pragma unroll
            for (int j = 0; j < 4; ++j) acc[mt][nt][j] = 0.f;

#define ISSUE_STAGE(st, buf)                                                    \
    do {                                                                        \
        const int k0 = (st) * KT;                                               \
        const uint32_t sb = (uint32_t)((buf) * STH * 2);                        \
        _Pragma("unroll")                                                       \
        for (int q = 0; q < 4; ++q) {                                           \
            cpasync16(aDst + sb + q * 32 * PITCH * 2,                           \
                      aSrc + (size_t)q * 32 * HH + k0);                         \
            cpasync16(bDst + sb + q * 32 * PITCH * 2,                           \
                      bSrc + (size_t)q * 32 * HH + k0);                         \
        }                                                                       \
    } while (0)

    ISSUE_STAGE(0, 0); CP_COMMIT();
    ISSUE_STAGE(1, 1); CP_COMMIT();
    ISSUE_STAGE(2, 2); CP_COMMIT();

    const int NSTAGES = HH / KT;   // 32
    for (int st = 0; st < NSTAGES; ++st) {
        CP_WAIT2();
        __syncthreads();

        const uint32_t baseA = smu + (uint32_t)((st & 3) * STH * 2);
        const uint32_t baseB = baseA + OPH * 2;
#pragma unroll
        for (int kk = 0; kk < KT; kk += 16) {
            const uint32_t kb = (uint32_t)(kk * 2);
            uint32_t af[4][4], bf[4][4];
#pragma unroll
            for (int mt = 0; mt < 4; ++mt) ldsm4(af[mt], baseA + aoffb[mt] + kb);
#pragma unroll
            for (int j = 0; j < 4; ++j)    ldsm4(bf[j],  baseB + boffb[j] + kb);
#pragma unroll
            for (int mt = 0; mt < 4; ++mt)
#pragma unroll
                for (int nt = 0; nt < 8; ++nt) {
                    uint32_t bb[2] = {bf[nt >> 1][(nt & 1) ? 1 : 0],
                                      bf[nt >> 1][(nt & 1) ? 3 : 2]};
                    mma16816(acc[mt][nt], af[mt], bb);
                }
        }
        if (st + 3 < NSTAGES) ISSUE_STAGE(st + 3, (st + 3) & 3);
        CP_COMMIT();
    }

    // Epilogue
    const int lr = lane >> 2, lc = (lane & 3) * 2;
    float* C = Out + (size_t)b * SS * HH;
#pragma unroll
    for (int mt = 0; mt < 4; ++mt)
#pragma unroll
        for (int nt = 0; nt < 8; ++nt) {
            int r = crow + m0 + mt * 16 + lr;
            int c = ccol + n0 + nt * 8 + lc;
            *reinterpret_cast<float2*>(&C[(size_t)r * HH + c]) =
                make_float2(acc[mt][nt][0], acc[mt][nt][1]);
            *reinterpret_cast<float2*>(&C[(size_t)(r + 8) * HH + c]) =
                make_float2(acc[mt][nt][2], acc[mt][nt][3]);
        }
}

// ---------------------------------------------------------------------------
extern "C" void kernel_launch(void* const* d_in, const int* in_sizes, int n_in,
                              void* d_out, int out_size) {
    const float* x = (const float*)d_in[0];   // [4,2048,1024]
    const float* W = (const float*)d_in[1];   // [1024,1024]
    float* out = (float*)d_out;               // [4,2048,1024]

    cudaFuncSetAttribute(gemm_mma, cudaFuncAttributeMaxDynamicSharedMemorySize,
                         GEMM_SMEM);

    gram_mma<<<dim3(BB * NH, SPL), 256>>>(x);
    combine_kernel<<<dim3(BB * NH, 4), 256>>>(W);
    gemm_mma<<<dim3(HH / 128, SS / 128, BB), 128, GEMM_SMEM>>>(out);
}